// round 16
// baseline (speedup 1.0000x reference)
#include <cuda_runtime.h>

// Packed per-node {T, cp}: each endpoint gather is ONE 8-byte access
// (1 L1tex wavefront per lane). 1 MB static __device__ storage.
#define MAX_NODES 131072
__device__ float2 g_tc[MAX_NODES];

// Kernel 1: pack the node table (out is zeroed by a memset node).
__global__ void prep_kernel(const float* __restrict__ T,
                            const float* __restrict__ cp, int n) {
    int i = blockIdx.x * blockDim.x + threadIdx.x;
    if (i < n) g_tc[i] = make_float2(T[i], cp[i]);
}

// Gather with L1 evict-last: node-table lines keep L1 residency against the
// 128 MB of streaming edge traffic. ncu-verified win: kernel 87.1 -> 78.3 us.
__device__ __forceinline__ float2 gather_node(const float2* __restrict__ p) {
    float2 v;
    asm volatile("ld.global.nc.L1::evict_last.v2.f32 {%0, %1}, [%2];"
                 : "=f"(v.x), "=f"(v.y) : "l"(p));
    return v;
}

__device__ __forceinline__ void edge_op(float Ts, float cps, float Td, float cpd,
                                        float L, float C, float A, float t,
                                        int si, int di, float* out) {
    float dT = Ts - Td;
    // relu: ~50% of random edges have dT <= 0 -> E == 0 exactly -> skip the
    // two REDG lanes and all the math.
    if (dT > 0.0f) {
        float x   = __fdividef(dT, L) * C;             // gradient * conductivity
        float hfd = exp2f(0.33333334f * __log2f(x));   // cbrt via 2 MUFU
        float Ec  = hfd * A * t;                        // conduction-limited energy
        float ccp = __fdividef(cpd * cps, cpd + cps);   // series thermal capacity
        float E   = fminf(Ec, dT * ccp);
        atomicAdd(out + di,  E);   // heat received (REDG, no return)
        atomicAdd(out + si, -E);   // heat sent
    }
}

// Kernel 2: FOUR edges per thread — the measured optimum (R12 showed 8 edges
// regresses: per-warp 16-gather bursts overrun the L1tex wavefront queue and
// occupancy halves). 8 independent evict-last gathers (MLP=8) + 5 coalesced
// 128-bit stream loads per thread; 40 regs, occ ~65%.
__global__ void __launch_bounds__(256)
edge_kernel(const float* __restrict__ L, const float* __restrict__ C,
            const float* __restrict__ A, const int* __restrict__ S,
            const int* __restrict__ D, const float* __restrict__ ts,
            float* __restrict__ out, int nq, int ne) {
    int q = blockIdx.x * blockDim.x + threadIdx.x;
    if (q >= nq) return;
    float t = __ldg(ts);
    int e0 = q * 4;
    if (e0 + 3 < ne) {
        int4   s = __ldg(reinterpret_cast<const int4*>(S) + q);
        int4   d = __ldg(reinterpret_cast<const int4*>(D) + q);
        float4 l = __ldg(reinterpret_cast<const float4*>(L) + q);
        float4 c = __ldg(reinterpret_cast<const float4*>(C) + q);
        float4 a = __ldg(reinterpret_cast<const float4*>(A) + q);

        // Issue all 8 gathers up front (independent -> overlapped in LSU).
        float2 n0s = gather_node(g_tc + s.x), n0d = gather_node(g_tc + d.x);
        float2 n1s = gather_node(g_tc + s.y), n1d = gather_node(g_tc + d.y);
        float2 n2s = gather_node(g_tc + s.z), n2d = gather_node(g_tc + d.z);
        float2 n3s = gather_node(g_tc + s.w), n3d = gather_node(g_tc + d.w);

        edge_op(n0s.x, n0s.y, n0d.x, n0d.y, l.x, c.x, a.x, t, s.x, d.x, out);
        edge_op(n1s.x, n1s.y, n1d.x, n1d.y, l.y, c.y, a.y, t, s.y, d.y, out);
        edge_op(n2s.x, n2s.y, n2d.x, n2d.y, l.z, c.z, a.z, t, s.z, d.z, out);
        edge_op(n3s.x, n3s.y, n3d.x, n3d.y, l.w, c.w, a.w, t, s.w, d.w, out);
    } else {
        // scalar tail (ne % 4 != 0); for this problem ne = 6,400,000 so unused
        for (int e = e0; e < ne; ++e) {
            int si = S[e], di = D[e];
            float2 ns = g_tc[si], nd = g_tc[di];
            edge_op(ns.x, ns.y, nd.x, nd.y, L[e], C[e], A[e], t, si, di, out);
        }
    }
}

extern "C" void kernel_launch(void* const* d_in, const int* in_sizes, int n_in,
                              void* d_out, int out_size) {
    const float* T    = (const float*)d_in[0];
    const float* cp   = (const float*)d_in[1];
    const float* L    = (const float*)d_in[2];
    const float* cond = (const float*)d_in[3];
    const float* A    = (const float*)d_in[4];
    const float* ts   = (const float*)d_in[5];
    const int*   src  = (const int*)d_in[6];
    const int*   dst  = (const int*)d_in[7];
    float*       out  = (float*)d_out;

    int n  = in_sizes[0];   // nodes (== out_size)
    int ne = in_sizes[2];   // edges

    // Zero accumulator via a memset node; prep only packs the node table.
    cudaMemsetAsync(out, 0, (size_t)n * sizeof(float));
    prep_kernel<<<(n + 255) / 256, 256>>>(T, cp, n);

    int nq = (ne + 3) / 4;
    edge_kernel<<<(nq + 255) / 256, 256>>>(L, cond, A, src, dst, ts, out, nq, ne);
}

// round 17
// speedup vs baseline: 1.4592x; 1.4592x over previous
#include <cuda_runtime.h>

// Packed per-node {T, cp}: each endpoint gather is ONE 8-byte access
// (1 L1tex wavefront per lane). 1 MB static __device__ storage.
#define MAX_NODES 131072
__device__ float2 g_tc[MAX_NODES];

// Kernel 1: pack the node table (out is zeroed by a memset node).
__global__ void prep_kernel(const float* __restrict__ T,
                            const float* __restrict__ cp, int n) {
    int i = blockIdx.x * blockDim.x + threadIdx.x;
    if (i < n) g_tc[i] = make_float2(T[i], cp[i]);
}

// Gather with L1 evict-last: node-table lines keep L1 residency against the
// 128 MB of streaming edge traffic. ncu-verified win in same-session A/B
// (R5->R11: kernel 87.1 -> 78.3 us at ~2.0 GHz clocks).
__device__ __forceinline__ float2 gather_node(const float2* __restrict__ p) {
    float2 v;
    asm volatile("ld.global.nc.L1::evict_last.v2.f32 {%0, %1}, [%2];"
                 : "=f"(v.x), "=f"(v.y) : "l"(p));
    return v;
}

__device__ __forceinline__ void edge_op(float Ts, float cps, float Td, float cpd,
                                        float L, float C, float A, float t,
                                        int si, int di, float* out) {
    float dT = Ts - Td;
    // relu: ~50% of random edges have dT <= 0 -> E == 0 exactly -> skip the
    // two REDG lanes and all the math.
    if (dT > 0.0f) {
        float x   = __fdividef(dT, L) * C;             // gradient * conductivity
        float hfd = exp2f(0.33333334f * __log2f(x));   // cbrt via 2 MUFU
        float Ec  = hfd * A * t;                        // conduction-limited energy
        float ccp = __fdividef(cpd * cps, cpd + cps);   // series thermal capacity
        float E   = fminf(Ec, dT * ccp);
        atomicAdd(out + di,  E);   // heat received (REDG, no return)
        atomicAdd(out + si, -E);   // heat sent
    }
}

// Kernel 2: FOUR edges per thread — the measured optimum across R5-R12:
//   - 8 edges/thread (R12): regression (16-gather bursts overrun L1tex queue,
//     occupancy halves to 33%).
//   - occupancy boost / stage-splitting / stream evict-first / DSMEM: all
//     measured neutral or negative.
// 8 independent evict-last gathers (MLP=8) + 5 coalesced 128-bit stream
// loads per thread; 40 regs, occ ~65%. Sits at the L1tex lane-event floor
// (~150K LSU cyc/SM: 12.8M gather wavefronts + ~6.4M REDG lanes).
__global__ void __launch_bounds__(256)
edge_kernel(const float* __restrict__ L, const float* __restrict__ C,
            const float* __restrict__ A, const int* __restrict__ S,
            const int* __restrict__ D, const float* __restrict__ ts,
            float* __restrict__ out, int nq, int ne) {
    int q = blockIdx.x * blockDim.x + threadIdx.x;
    if (q >= nq) return;
    float t = __ldg(ts);
    int e0 = q * 4;
    if (e0 + 3 < ne) {
        int4   s = __ldg(reinterpret_cast<const int4*>(S) + q);
        int4   d = __ldg(reinterpret_cast<const int4*>(D) + q);
        float4 l = __ldg(reinterpret_cast<const float4*>(L) + q);
        float4 c = __ldg(reinterpret_cast<const float4*>(C) + q);
        float4 a = __ldg(reinterpret_cast<const float4*>(A) + q);

        // Issue all 8 gathers up front (independent -> overlapped in LSU).
        float2 n0s = gather_node(g_tc + s.x), n0d = gather_node(g_tc + d.x);
        float2 n1s = gather_node(g_tc + s.y), n1d = gather_node(g_tc + d.y);
        float2 n2s = gather_node(g_tc + s.z), n2d = gather_node(g_tc + d.z);
        float2 n3s = gather_node(g_tc + s.w), n3d = gather_node(g_tc + d.w);

        edge_op(n0s.x, n0s.y, n0d.x, n0d.y, l.x, c.x, a.x, t, s.x, d.x, out);
        edge_op(n1s.x, n1s.y, n1d.x, n1d.y, l.y, c.y, a.y, t, s.y, d.y, out);
        edge_op(n2s.x, n2s.y, n2d.x, n2d.y, l.z, c.z, a.z, t, s.z, d.z, out);
        edge_op(n3s.x, n3s.y, n3d.x, n3d.y, l.w, c.w, a.w, t, s.w, d.w, out);
    } else {
        // scalar tail (ne % 4 != 0); for this problem ne = 6,400,000 so unused
        for (int e = e0; e < ne; ++e) {
            int si = S[e], di = D[e];
            float2 ns = g_tc[si], nd = g_tc[di];
            edge_op(ns.x, ns.y, nd.x, nd.y, L[e], C[e], A[e], t, si, di, out);
        }
    }
}

extern "C" void kernel_launch(void* const* d_in, const int* in_sizes, int n_in,
                              void* d_out, int out_size) {
    const float* T    = (const float*)d_in[0];
    const float* cp   = (const float*)d_in[1];
    const float* L    = (const float*)d_in[2];
    const float* cond = (const float*)d_in[3];
    const float* A    = (const float*)d_in[4];
    const float* ts   = (const float*)d_in[5];
    const int*   src  = (const int*)d_in[6];
    const int*   dst  = (const int*)d_in[7];
    float*       out  = (float*)d_out;

    int n  = in_sizes[0];   // nodes (== out_size)
    int ne = in_sizes[2];   // edges

    // Zero accumulator via a memset node; prep only packs the node table.
    cudaMemsetAsync(out, 0, (size_t)n * sizeof(float));
    prep_kernel<<<(n + 255) / 256, 256>>>(T, cp, n);

    int nq = (ne + 3) / 4;
    edge_kernel<<<(nq + 255) / 256, 256>>>(L, cond, A, src, dst, ts, out, nq, ne);
}